// round 8
// baseline (speedup 1.0000x reference)
#include <cuda_runtime.h>
#include <cuda_bf16.h>
#include <math.h>

#define B_SZ 4
#define T_LEN 1024
#define D_MODEL 128
#define D_STATE 64
#define ED 256
#define DT_RANK 8
#define ROWS (B_SZ * T_LEN)          // 4096
#define EPS 1e-5f
#define LOG2E 1.44269504088896340736f

// ---------------- scratch (device globals; no allocation allowed) -------------
__device__ float g_z[ROWS * D_MODEL];        // z residual
__device__ float g_zn[ROWS * D_MODEL];       // rmsnorm(z)
__device__ float g_xz[ROWS * 2 * ED];        // in_proj output (xs_raw | zg)
__device__ float g_xs[ROWS * ED];            // conv+silu output
__device__ float g_dbc[ROWS * 136];          // x_proj output (dt|B|C)
__device__ float g_delta_t[B_SZ * ED * T_LEN]; // delta, (b,e,t) layout
__device__ float g_dxs_t[B_SZ * ED * T_LEN];   // delta*xs, (b,e,t) layout
__device__ float g_yg[ROWS * ED];            // gated scan output
__device__ float g_core[ROWS * D_MODEL];     // out_proj output

// ---------------- helpers ------------------------------------------------------
__device__ __forceinline__ float f2tf32(float x) {
    float r;
    asm("cvt.rna.tf32.f32 %0, %1;" : "=f"(r) : "f"(x));
    return r;
}
__device__ __forceinline__ unsigned fbits(float x) { return __float_as_uint(x); }

// ---------------- kernel 1: z = z_seq + aux@auxW^T + aux_b ; zn = rmsnorm(z) --
__global__ void pre_kernel(const float* __restrict__ z_seq,
                           const float* __restrict__ aux_t,
                           const float* __restrict__ aux_W,
                           const float* __restrict__ aux_b,
                           const float* __restrict__ rms_w) {
    int row = blockIdx.x;                // b*T + t
    int d = threadIdx.x;                 // 0..127
    float a0 = aux_t[row * 3 + 0];
    float a1 = aux_t[row * 3 + 1];
    float a2 = aux_t[row * 3 + 2];
    float z = z_seq[row * D_MODEL + d]
            + a0 * aux_W[d * 3 + 0] + a1 * aux_W[d * 3 + 1] + a2 * aux_W[d * 3 + 2]
            + aux_b[d];
    float s = z * z;
    #pragma unroll
    for (int o = 16; o; o >>= 1) s += __shfl_xor_sync(0xffffffffu, s, o);
    __shared__ float ws[4];
    if ((d & 31) == 0) ws[d >> 5] = s;
    __syncthreads();
    float ms = (ws[0] + ws[1] + ws[2] + ws[3]) * (1.0f / 128.0f);
    float zn = z * rsqrtf(ms + EPS) * rms_w[d];
    g_z[row * D_MODEL + d] = z;
    g_zn[row * D_MODEL + d] = zn;
}

// ---------------- tf32 tensor-core NT GEMM: C[m][n] = sum_k A[m][k]*B[n][k] ---
// BM=64, BN=64, BK=16, 256 threads (8 warps as 2m x 4n), warp tile 32x16.
// Smem holds tf32-rounded values in a k-permuted layout so every mma fragment
// load is a single LDS.64:  k' = kb*8 + 2*(k&3) + ((k>>2)&1)  within each k8.
#define BM 64
#define BN 64
#define BK 16
__global__ __launch_bounds__(256) void gemm_tf32_nt(
    const float* __restrict__ A, const float* __restrict__ B,
    float* __restrict__ C, int M, int N, int K) {
    __shared__ float As[BM][BK + 2];
    __shared__ float Bs[BN][BK + 2];
    const int tid  = threadIdx.x;
    const int lane = tid & 31;
    const int w    = tid >> 5;
    const int wm   = w & 1;            // 2 m groups (32 rows each)
    const int wn   = w >> 1;           // 4 n groups (16 cols each)
    const int g    = lane >> 2;        // 0..7
    const int tig  = lane & 3;         // 0..3
    const int m0   = blockIdx.y * BM;
    const int n0   = blockIdx.x * BN;

    const int lr  = tid >> 2;          // load row 0..63
    const int lk4 = tid & 3;           // float4 index over BK
    const int kb_ld   = lk4 >> 1;
    const int half_ld = lk4 & 1;
    const int kbase   = kb_ld * 8 + half_ld;

    float c[2][2][4] = {};

    for (int k0 = 0; k0 < K; k0 += BK) {
        // A tile 64x16
        {
            float4 v = *(const float4*)&A[(size_t)(m0 + lr) * K + k0 + lk4 * 4];
            float* dst = &As[lr][kbase];
            dst[0] = f2tf32(v.x); dst[2] = f2tf32(v.y);
            dst[4] = f2tf32(v.z); dst[6] = f2tf32(v.w);
        }
        // B tile 64x16 (guard N)
        {
            float4 v = make_float4(0.f, 0.f, 0.f, 0.f);
            if (n0 + lr < N)
                v = *(const float4*)&B[(size_t)(n0 + lr) * K + k0 + lk4 * 4];
            float* dst = &Bs[lr][kbase];
            dst[0] = f2tf32(v.x); dst[2] = f2tf32(v.y);
            dst[4] = f2tf32(v.z); dst[6] = f2tf32(v.w);
        }
        __syncthreads();
        #pragma unroll
        for (int kb = 0; kb < 2; ++kb) {
            unsigned a[2][4], bf[2][2];
            #pragma unroll
            for (int mt = 0; mt < 2; ++mt) {
                int mr = wm * 32 + mt * 16;
                float2 lo = *(const float2*)&As[mr + g][kb * 8 + 2 * tig];
                float2 hi = *(const float2*)&As[mr + g + 8][kb * 8 + 2 * tig];
                a[mt][0] = fbits(lo.x); a[mt][2] = fbits(lo.y);
                a[mt][1] = fbits(hi.x); a[mt][3] = fbits(hi.y);
            }
            #pragma unroll
            for (int nt = 0; nt < 2; ++nt) {
                int nr = wn * 16 + nt * 8;
                float2 bv = *(const float2*)&Bs[nr + g][kb * 8 + 2 * tig];
                bf[nt][0] = fbits(bv.x); bf[nt][1] = fbits(bv.y);
            }
            #pragma unroll
            for (int mt = 0; mt < 2; ++mt)
                #pragma unroll
                for (int nt = 0; nt < 2; ++nt)
                    asm volatile(
                        "mma.sync.aligned.m16n8k8.row.col.f32.tf32.tf32.f32 "
                        "{%0,%1,%2,%3}, {%4,%5,%6,%7}, {%8,%9}, {%0,%1,%2,%3};"
                        : "+f"(c[mt][nt][0]), "+f"(c[mt][nt][1]),
                          "+f"(c[mt][nt][2]), "+f"(c[mt][nt][3])
                        : "r"(a[mt][0]), "r"(a[mt][1]), "r"(a[mt][2]), "r"(a[mt][3]),
                          "r"(bf[nt][0]), "r"(bf[nt][1]));
        }
        __syncthreads();
    }
    #pragma unroll
    for (int mt = 0; mt < 2; ++mt) {
        int r = m0 + wm * 32 + mt * 16 + g;
        #pragma unroll
        for (int nt = 0; nt < 2; ++nt) {
            int cb = n0 + wn * 16 + nt * 8 + 2 * tig;
            if (cb < N) {
                *(float2*)&C[(size_t)r * N + cb] =
                    make_float2(c[mt][nt][0], c[mt][nt][1]);
                *(float2*)&C[(size_t)(r + 8) * N + cb] =
                    make_float2(c[mt][nt][2], c[mt][nt][3]);
            }
        }
    }
}

// ---------------- kernel 3: depthwise causal conv(4) + bias + silu ------------
__global__ void conv_kernel(const float* __restrict__ conv_W,
                            const float* __restrict__ conv_b) {
    int idx = blockIdx.x * blockDim.x + threadIdx.x;   // over ROWS*ED
    if (idx >= ROWS * ED) return;
    int e = idx & (ED - 1);
    int bt = idx >> 8;
    int t = bt & (T_LEN - 1);
    int b = bt >> 10;
    float acc = conv_b[e];
    #pragma unroll
    for (int k = 0; k < 4; ++k) {
        int tt = t - 3 + k;
        if (tt >= 0)
            acc = fmaf(g_xz[(size_t)(b * T_LEN + tt) * (2 * ED) + e], conv_W[e * 4 + k], acc);
    }
    float s = acc / (1.0f + __expf(-acc));   // silu
    g_xs[idx] = s;
}

// ---------------- kernel 5: delta = softplus(dt @ dtW^T + dt_b); dxs ----------
__global__ __launch_bounds__(256) void delta_kernel(
    const float* __restrict__ dt_W, const float* __restrict__ dt_b) {
    int b = blockIdx.y;
    int t0 = blockIdx.x * 64;
    __shared__ float sdt[64][9];
    __shared__ float sW[ED * 8];
    __shared__ float sb[ED];
    int tid = threadIdx.x;
    if (tid < 128) {
        int r = tid >> 1, h = tid & 1;
        float4 v = *(const float4*)&g_dbc[(size_t)(b * T_LEN + t0 + r) * 136 + h * 4];
        sdt[r][h * 4 + 0] = v.x; sdt[r][h * 4 + 1] = v.y;
        sdt[r][h * 4 + 2] = v.z; sdt[r][h * 4 + 3] = v.w;
    }
    for (int i = tid; i < ED * 8; i += 256) sW[i] = dt_W[i];
    if (tid < ED) sb[tid] = dt_b[tid];
    __syncthreads();
    int tx = tid & 63;
    int ey = tid >> 6;
    for (int e = ey; e < ED; e += 4) {
        float acc = sb[e];
        #pragma unroll
        for (int r = 0; r < 8; ++r) acc = fmaf(sdt[tx][r], sW[e * 8 + r], acc);
        float dl = (acc > 20.0f) ? acc : log1pf(expf(acc));
        size_t o = ((size_t)b * ED + e) * T_LEN + t0 + tx;
        g_delta_t[o] = dl;
        g_dxs_t[o] = dl * g_xs[(size_t)(b * T_LEN + t0 + tx) * ED + e];
    }
}

// ---------------- kernel 6: selective scan + fused gate ------------------------
// CTA: (e-tile of 8, b). Warp w owns e=e0+w; lane owns states {2l, 2l+1}.
// Epilogue applies yg = (y + D*xs) * silu(zg) directly.
#define CT 64
__global__ __launch_bounds__(256) void scan_kernel(const float* __restrict__ A_log,
                                                   const float* __restrict__ D_param) {
    __shared__ float sB[CT][64];
    __shared__ float sC[CT][64];
    __shared__ float sD[8][CT];
    __shared__ float sDX[8][CT];
    __shared__ float sY[8][CT];
    __shared__ float sDp[8];
    int b = blockIdx.y;
    int e0 = blockIdx.x * 8;
    int tid = threadIdx.x;
    int w = tid >> 5, lane = tid & 31;
    int e = e0 + w;
    if (tid < 8) sDp[tid] = D_param[e0 + tid];
    float k0 = -expf(A_log[e * D_STATE + 2 * lane])     * LOG2E;
    float k1 = -expf(A_log[e * D_STATE + 2 * lane + 1]) * LOG2E;
    float h0 = 0.f, h1 = 0.f;
    const float* dT  = g_delta_t + ((size_t)b * ED + e) * T_LEN;
    const float* dxT = g_dxs_t   + ((size_t)b * ED + e) * T_LEN;
    for (int t0 = 0; t0 < T_LEN; t0 += CT) {
        // stage B/C tiles (shared by all 8 e's)
        #pragma unroll
        for (int idx = tid; idx < CT * 16; idx += 256) {
            int r = idx >> 4, c4 = idx & 15;
            const float* row = &g_dbc[(size_t)(b * T_LEN + t0 + r) * 136];
            float4 vb = *(const float4*)(row + DT_RANK + c4 * 4);
            float4 vc = *(const float4*)(row + DT_RANK + D_STATE + c4 * 4);
            *(float4*)&sB[r][c4 * 4] = vb;
            *(float4*)&sC[r][c4 * 4] = vc;
        }
        sD[w][lane]       = dT[t0 + lane];
        sD[w][lane + 32]  = dT[t0 + lane + 32];
        sDX[w][lane]      = dxT[t0 + lane];
        sDX[w][lane + 32] = dxT[t0 + lane + 32];
        __syncthreads();
        #pragma unroll 4
        for (int t = 0; t < CT; ++t) {
            float d  = sD[w][t];
            float dx = sDX[w][t];
            float a0 = exp2f(d * k0);
            float a1 = exp2f(d * k1);
            float2 Bv = *(const float2*)&sB[t][2 * lane];
            float2 Cv = *(const float2*)&sC[t][2 * lane];
            h0 = fmaf(a0, h0, dx * Bv.x);
            h1 = fmaf(a1, h1, dx * Bv.y);
            float p = h0 * Cv.x + h1 * Cv.y;
            #pragma unroll
            for (int o = 16; o; o >>= 1) p += __shfl_xor_sync(0xffffffffu, p, o);
            if (lane == 0) sY[w][t] = p;
        }
        __syncthreads();
        // fused gate epilogue: yg = (y + D*xs) * silu(zg), (b,t,e) layout
        #pragma unroll
        for (int idx = tid; idx < 8 * CT; idx += 256) {
            int j = idx & 7, tt = idx >> 3;
            size_t row = (size_t)(b * T_LEN + t0 + tt);
            float xs = g_xs[row * ED + e0 + j];
            float zg = g_xz[row * (2 * ED) + ED + e0 + j];
            float sg = zg / (1.0f + __expf(-zg));
            g_yg[row * ED + e0 + j] = (sY[j][tt] + sDp[j] * xs) * sg;
        }
        // next iteration's load phase only touches sB/sC/sD/sDX (disjoint from
        // sY); sY is rewritten only after the next post-load __syncthreads.
    }
}

// ---------------- kernel 9: r = core + 2z; LayerNorm ---------------------------
__global__ void ln_kernel(const float* __restrict__ ln_w,
                          const float* __restrict__ ln_b,
                          float* __restrict__ out) {
    int row = blockIdx.x;
    int d = threadIdx.x;
    float r = g_core[row * D_MODEL + d] + 2.0f * g_z[row * D_MODEL + d];
    float s = r;
    #pragma unroll
    for (int o = 16; o; o >>= 1) s += __shfl_xor_sync(0xffffffffu, s, o);
    __shared__ float a4[4], b4[4];
    if ((d & 31) == 0) a4[d >> 5] = s;
    __syncthreads();
    float mu = (a4[0] + a4[1] + a4[2] + a4[3]) * (1.0f / 128.0f);
    float c = r - mu;
    float q = c * c;
    #pragma unroll
    for (int o = 16; o; o >>= 1) q += __shfl_xor_sync(0xffffffffu, q, o);
    if ((d & 31) == 0) b4[d >> 5] = q;
    __syncthreads();
    float var = (b4[0] + b4[1] + b4[2] + b4[3]) * (1.0f / 128.0f);
    out[row * D_MODEL + d] = c * rsqrtf(var + EPS) * ln_w[d] + ln_b[d];
}

// ---------------- launch --------------------------------------------------------
extern "C" void kernel_launch(void* const* d_in, const int* in_sizes, int n_in,
                              void* d_out, int out_size) {
    const float* z_seq      = (const float*)d_in[0];
    const float* aux_tensor = (const float*)d_in[1];
    const float* aux_W      = (const float*)d_in[2];
    const float* aux_b      = (const float*)d_in[3];
    const float* ln_w       = (const float*)d_in[4];
    const float* ln_b       = (const float*)d_in[5];
    const float* rms_w      = (const float*)d_in[6];
    const float* in_proj_W  = (const float*)d_in[7];
    const float* conv_W     = (const float*)d_in[8];
    const float* conv_b     = (const float*)d_in[9];
    const float* x_proj_W   = (const float*)d_in[10];
    const float* dt_W       = (const float*)d_in[11];
    const float* dt_b       = (const float*)d_in[12];
    const float* A_log      = (const float*)d_in[13];
    const float* D_param    = (const float*)d_in[14];
    const float* out_proj_W = (const float*)d_in[15];
    float* out = (float*)d_out;

    float *p_zn, *p_xz, *p_xs, *p_dbc, *p_yg, *p_core;
    cudaGetSymbolAddress((void**)&p_zn,   g_zn);
    cudaGetSymbolAddress((void**)&p_xz,   g_xz);
    cudaGetSymbolAddress((void**)&p_xs,   g_xs);
    cudaGetSymbolAddress((void**)&p_dbc,  g_dbc);
    cudaGetSymbolAddress((void**)&p_yg,   g_yg);
    cudaGetSymbolAddress((void**)&p_core, g_core);

    // 1. pre: z + rmsnorm
    pre_kernel<<<ROWS, 128>>>(z_seq, aux_tensor, aux_W, aux_b, rms_w);

    // 2. in_proj: xz = zn @ in_proj_W^T   (4096 x 512, K=128)  [tf32 MMA]
    gemm_tf32_nt<<<dim3(512 / BN, ROWS / BM), 256>>>(p_zn, in_proj_W, p_xz,
                                                     ROWS, 2 * ED, D_MODEL);

    // 3. depthwise conv + silu
    conv_kernel<<<(ROWS * ED) / 256, 256>>>(conv_W, conv_b);

    // 4. x_proj: dbc = xs @ x_proj_W^T    (4096 x 136, K=256)  [tf32 MMA]
    gemm_tf32_nt<<<dim3(3, ROWS / BM), 256>>>(p_xs, x_proj_W, p_dbc,
                                              ROWS, 136, ED);

    // 5. delta + dxs (transposed (b,e,t) layout for the scan)
    delta_kernel<<<dim3(T_LEN / 64, B_SZ), 256>>>(dt_W, dt_b);

    // 6. selective scan + fused gate
    scan_kernel<<<dim3(ED / 8, B_SZ), 256>>>(A_log, D_param);

    // 7. out_proj: core = yg @ out_proj_W^T   (4096 x 128, K=256)  [tf32 MMA]
    gemm_tf32_nt<<<dim3(2, ROWS / BM), 256>>>(p_yg, out_proj_W, p_core,
                                              ROWS, D_MODEL, ED);

    // 8. residual (core + 2z) + LayerNorm
    ln_kernel<<<ROWS, 128>>>(ln_w, ln_b, out);
}

// round 9
// speedup vs baseline: 1.5343x; 1.5343x over previous
#include <cuda_runtime.h>
#include <cuda_bf16.h>
#include <math.h>

#define B_SZ 4
#define T_LEN 1024
#define D_MODEL 128
#define D_STATE 64
#define ED 256
#define DT_RANK 8
#define ROWS (B_SZ * T_LEN)          // 4096
#define EPS 1e-5f
#define LOG2E 1.44269504088896340736f

// ---------------- scratch (device globals; no allocation allowed) -------------
__device__ float g_z[ROWS * D_MODEL];        // z residual
__device__ float g_zn[ROWS * D_MODEL];       // rmsnorm(z)
__device__ float g_xz[ROWS * 2 * ED];        // in_proj output (xs_raw | zg)
__device__ float g_xs[ROWS * ED];            // conv+silu output
__device__ float g_dbc[ROWS * 136];          // x_proj output (dt|B|C)
__device__ float g_delta_t[B_SZ * ED * T_LEN]; // delta, (b,e,t) layout
__device__ float g_dxs_t[B_SZ * ED * T_LEN];   // delta*xs, (b,e,t) layout
__device__ float g_yg[ROWS * ED];            // gated scan output
__device__ float g_core[ROWS * D_MODEL];     // out_proj output

// ---------------- helpers ------------------------------------------------------
__device__ __forceinline__ float f2tf32(float x) {
    float r;
    asm("cvt.rna.tf32.f32 %0, %1;" : "=f"(r) : "f"(x));
    return r;
}
__device__ __forceinline__ unsigned fbits(float x) { return __float_as_uint(x); }

// ---------------- kernel 1: z = z_seq + aux@auxW^T + aux_b ; zn = rmsnorm(z) --
__global__ void pre_kernel(const float* __restrict__ z_seq,
                           const float* __restrict__ aux_t,
                           const float* __restrict__ aux_W,
                           const float* __restrict__ aux_b,
                           const float* __restrict__ rms_w) {
    int row = blockIdx.x;                // b*T + t
    int d = threadIdx.x;                 // 0..127
    float a0 = aux_t[row * 3 + 0];
    float a1 = aux_t[row * 3 + 1];
    float a2 = aux_t[row * 3 + 2];
    float z = z_seq[row * D_MODEL + d]
            + a0 * aux_W[d * 3 + 0] + a1 * aux_W[d * 3 + 1] + a2 * aux_W[d * 3 + 2]
            + aux_b[d];
    float s = z * z;
    #pragma unroll
    for (int o = 16; o; o >>= 1) s += __shfl_xor_sync(0xffffffffu, s, o);
    __shared__ float ws[4];
    if ((d & 31) == 0) ws[d >> 5] = s;
    __syncthreads();
    float ms = (ws[0] + ws[1] + ws[2] + ws[3]) * (1.0f / 128.0f);
    float zn = z * rsqrtf(ms + EPS) * rms_w[d];
    g_z[row * D_MODEL + d] = z;
    g_zn[row * D_MODEL + d] = zn;
}

// ---------------- tf32 tensor-core NT GEMM, double buffered --------------------
// C[m][n] = sum_k A[m][k] * B[n][k].
// BM=64, BN=64, BK=16, 256 threads (8 warps as 2m x 4n), warp tile 32x16.
// Smem holds tf32-rounded values in a k-permuted layout so every mma fragment
// load is a single LDS.64. Double-buffered: one __syncthreads per K-step,
// next tile's LDG issued before the MMA block so its latency is hidden.
#define BM 64
#define BN 64
#define BK 16
__global__ __launch_bounds__(256) void gemm_tf32_nt(
    const float* __restrict__ A, const float* __restrict__ B,
    float* __restrict__ C, int M, int N, int K) {
    __shared__ float As[2][BM][BK + 2];
    __shared__ float Bs[2][BN][BK + 2];
    const int tid  = threadIdx.x;
    const int lane = tid & 31;
    const int w    = tid >> 5;
    const int wm   = w & 1;            // 2 m groups (32 rows each)
    const int wn   = w >> 1;           // 4 n groups (16 cols each)
    const int g    = lane >> 2;        // 0..7
    const int tig  = lane & 3;         // 0..3
    const int m0   = blockIdx.y * BM;
    const int n0   = blockIdx.x * BN;

    const int lr  = tid >> 2;          // load row 0..63
    const int lk4 = tid & 3;           // float4 index over BK
    const int kbase = (lk4 >> 1) * 8 + (lk4 & 1);

    const float* Aptr = A + (size_t)(m0 + lr) * K + lk4 * 4;
    const bool   bok  = (n0 + lr) < N;
    const float* Bptr = B + (size_t)(bok ? (n0 + lr) : 0) * K + lk4 * 4;

    // prologue: tile 0
    float4 va = *(const float4*)Aptr;
    float4 vb = bok ? *(const float4*)Bptr : make_float4(0.f, 0.f, 0.f, 0.f);
    {
        float* da = &As[0][lr][kbase];
        da[0] = f2tf32(va.x); da[2] = f2tf32(va.y);
        da[4] = f2tf32(va.z); da[6] = f2tf32(va.w);
        float* db = &Bs[0][lr][kbase];
        db[0] = f2tf32(vb.x); db[2] = f2tf32(vb.y);
        db[4] = f2tf32(vb.z); db[6] = f2tf32(vb.w);
    }
    __syncthreads();

    float c[2][2][4] = {};
    const int nIter = K / BK;
    for (int i = 0; i < nIter; ++i) {
        const int cur = i & 1;
        // prefetch next tile (LDG early; latency covered by MMA below)
        if (i + 1 < nIter) {
            va = *(const float4*)(Aptr + (i + 1) * BK);
            vb = bok ? *(const float4*)(Bptr + (i + 1) * BK)
                     : make_float4(0.f, 0.f, 0.f, 0.f);
        }
        #pragma unroll
        for (int kb = 0; kb < 2; ++kb) {
            unsigned a[2][4], bf[2][2];
            #pragma unroll
            for (int mt = 0; mt < 2; ++mt) {
                int mr = wm * 32 + mt * 16;
                float2 lo = *(const float2*)&As[cur][mr + g][kb * 8 + 2 * tig];
                float2 hi = *(const float2*)&As[cur][mr + g + 8][kb * 8 + 2 * tig];
                a[mt][0] = fbits(lo.x); a[mt][2] = fbits(lo.y);
                a[mt][1] = fbits(hi.x); a[mt][3] = fbits(hi.y);
            }
            #pragma unroll
            for (int nt = 0; nt < 2; ++nt) {
                int nr = wn * 16 + nt * 8;
                float2 bv = *(const float2*)&Bs[cur][nr + g][kb * 8 + 2 * tig];
                bf[nt][0] = fbits(bv.x); bf[nt][1] = fbits(bv.y);
            }
            #pragma unroll
            for (int mt = 0; mt < 2; ++mt)
                #pragma unroll
                for (int nt = 0; nt < 2; ++nt)
                    asm volatile(
                        "mma.sync.aligned.m16n8k8.row.col.f32.tf32.tf32.f32 "
                        "{%0,%1,%2,%3}, {%4,%5,%6,%7}, {%8,%9}, {%0,%1,%2,%3};"
                        : "+f"(c[mt][nt][0]), "+f"(c[mt][nt][1]),
                          "+f"(c[mt][nt][2]), "+f"(c[mt][nt][3])
                        : "r"(a[mt][0]), "r"(a[mt][1]), "r"(a[mt][2]), "r"(a[mt][3]),
                          "r"(bf[nt][0]), "r"(bf[nt][1]));
        }
        // stage next tile into the alternate buffer
        if (i + 1 < nIter) {
            float* da = &As[cur ^ 1][lr][kbase];
            da[0] = f2tf32(va.x); da[2] = f2tf32(va.y);
            da[4] = f2tf32(va.z); da[6] = f2tf32(va.w);
            float* db = &Bs[cur ^ 1][lr][kbase];
            db[0] = f2tf32(vb.x); db[2] = f2tf32(vb.y);
            db[4] = f2tf32(vb.z); db[6] = f2tf32(vb.w);
        }
        __syncthreads();
    }
    #pragma unroll
    for (int mt = 0; mt < 2; ++mt) {
        int r = m0 + wm * 32 + mt * 16 + g;
        #pragma unroll
        for (int nt = 0; nt < 2; ++nt) {
            int cb = n0 + wn * 16 + nt * 8 + 2 * tig;
            if (cb < N) {
                *(float2*)&C[(size_t)r * N + cb] =
                    make_float2(c[mt][nt][0], c[mt][nt][1]);
                *(float2*)&C[(size_t)(r + 8) * N + cb] =
                    make_float2(c[mt][nt][2], c[mt][nt][3]);
            }
        }
    }
}

// ---------------- kernel 3: depthwise causal conv(4) + bias + silu ------------
__global__ void conv_kernel(const float* __restrict__ conv_W,
                            const float* __restrict__ conv_b) {
    int idx = blockIdx.x * blockDim.x + threadIdx.x;   // over ROWS*ED
    if (idx >= ROWS * ED) return;
    int e = idx & (ED - 1);
    int bt = idx >> 8;
    int t = bt & (T_LEN - 1);
    int b = bt >> 10;
    float acc = conv_b[e];
    #pragma unroll
    for (int k = 0; k < 4; ++k) {
        int tt = t - 3 + k;
        if (tt >= 0)
            acc = fmaf(g_xz[(size_t)(b * T_LEN + tt) * (2 * ED) + e], conv_W[e * 4 + k], acc);
    }
    float s = acc / (1.0f + __expf(-acc));   // silu
    g_xs[idx] = s;
}

// ---------------- kernel 5: delta = softplus(dt @ dtW^T + dt_b); dxs ----------
__global__ __launch_bounds__(256) void delta_kernel(
    const float* __restrict__ dt_W, const float* __restrict__ dt_b) {
    int b = blockIdx.y;
    int t0 = blockIdx.x * 64;
    __shared__ float sdt[64][9];
    __shared__ float sW[ED * 8];
    __shared__ float sb[ED];
    int tid = threadIdx.x;
    if (tid < 128) {
        int r = tid >> 1, h = tid & 1;
        float4 v = *(const float4*)&g_dbc[(size_t)(b * T_LEN + t0 + r) * 136 + h * 4];
        sdt[r][h * 4 + 0] = v.x; sdt[r][h * 4 + 1] = v.y;
        sdt[r][h * 4 + 2] = v.z; sdt[r][h * 4 + 3] = v.w;
    }
    for (int i = tid; i < ED * 8; i += 256) sW[i] = dt_W[i];
    if (tid < ED) sb[tid] = dt_b[tid];
    __syncthreads();
    int tx = tid & 63;
    int ey = tid >> 6;
    for (int e = ey; e < ED; e += 4) {
        float acc = sb[e];
        #pragma unroll
        for (int r = 0; r < 8; ++r) acc = fmaf(sdt[tx][r], sW[e * 8 + r], acc);
        float dl = (acc > 20.0f) ? acc : __logf(1.0f + __expf(acc));
        size_t o = ((size_t)b * ED + e) * T_LEN + t0 + tx;
        g_delta_t[o] = dl;
        g_dxs_t[o] = dl * g_xs[(size_t)(b * T_LEN + t0 + tx) * ED + e];
    }
}

// ---------------- kernel 6: selective scan + fused gate ------------------------
// CTA: (e-tile of 8, b). Warp w owns e=e0+w; lane owns states {2l, 2l+1}.
// Per t: one shfl16, lanes<16 store partials to smem; the 16-way reduction is
// merged into the gate epilogue pass (LDS.128 x4 per output element).
#define CT 32
__global__ __launch_bounds__(256) void scan_kernel(const float* __restrict__ A_log,
                                                   const float* __restrict__ D_param) {
    __shared__ float sB[CT][64];                  // 8 KB
    __shared__ float sC[CT][64];                  // 8 KB
    __shared__ float sD[8][CT];                   // 1 KB
    __shared__ float sDX[8][CT];                  // 1 KB
    __shared__ __align__(16) float sP[CT][8][20]; // 20.5 KB (16 used, pad to 20)
    __shared__ float sDp[8];
    int b = blockIdx.y;
    int e0 = blockIdx.x * 8;
    int tid = threadIdx.x;
    int w = tid >> 5, lane = tid & 31;
    int e = e0 + w;
    if (tid < 8) sDp[tid] = D_param[e0 + tid];
    float k0 = -__expf(A_log[e * D_STATE + 2 * lane])     * LOG2E;
    float k1 = -__expf(A_log[e * D_STATE + 2 * lane + 1]) * LOG2E;
    float h0 = 0.f, h1 = 0.f;
    const float* dT  = g_delta_t + ((size_t)b * ED + e) * T_LEN;
    const float* dxT = g_dxs_t   + ((size_t)b * ED + e) * T_LEN;
    const int jj = tid & 7, tt = tid >> 3;        // reduce-pass mapping
    for (int t0 = 0; t0 < T_LEN; t0 += CT) {
        // stage B/C tiles (shared by all 8 e's)
        #pragma unroll
        for (int idx = tid; idx < CT * 16; idx += 256) {
            int r = idx >> 4, c4 = idx & 15;
            const float* row = &g_dbc[(size_t)(b * T_LEN + t0 + r) * 136];
            float4 vbv = *(const float4*)(row + DT_RANK + c4 * 4);
            float4 vcv = *(const float4*)(row + DT_RANK + D_STATE + c4 * 4);
            *(float4*)&sB[r][c4 * 4] = vbv;
            *(float4*)&sC[r][c4 * 4] = vcv;
        }
        sD[w][lane]  = dT[t0 + lane];             // CT == 32 == warp size
        sDX[w][lane] = dxT[t0 + lane];
        __syncthreads();
        #pragma unroll 8
        for (int t = 0; t < CT; ++t) {
            float d  = sD[w][t];
            float dx = sDX[w][t];
            float a0 = exp2f(d * k0);
            float a1 = exp2f(d * k1);
            float2 Bv = *(const float2*)&sB[t][2 * lane];
            float2 Cv = *(const float2*)&sC[t][2 * lane];
            h0 = fmaf(a0, h0, dx * Bv.x);
            h1 = fmaf(a1, h1, dx * Bv.y);
            float p = h0 * Cv.x + h1 * Cv.y;
            p += __shfl_xor_sync(0xffffffffu, p, 16);
            if (lane < 16) sP[t][w][lane] = p;
        }
        __syncthreads();
        // reduce + gate: one (tt, jj) output element per thread
        {
            const float4* pp = (const float4*)&sP[tt][jj][0];
            float4 q0 = pp[0], q1 = pp[1], q2 = pp[2], q3 = pp[3];
            float y = ((q0.x + q0.y) + (q0.z + q0.w))
                    + ((q1.x + q1.y) + (q1.z + q1.w))
                    + ((q2.x + q2.y) + (q2.z + q2.w))
                    + ((q3.x + q3.y) + (q3.z + q3.w));
            size_t row = (size_t)(b * T_LEN + t0 + tt);
            float xs = g_xs[row * ED + e0 + jj];
            float zg = g_xz[row * (2 * ED) + ED + e0 + jj];
            float sg = zg / (1.0f + __expf(-zg));
            g_yg[row * ED + e0 + jj] = (y + sDp[jj] * xs) * sg;
        }
        // no extra sync: next load phase writes only sB/sC/sD/sDX (disjoint from
        // sP); sP is rewritten only after the next post-load __syncthreads.
    }
}

// ---------------- kernel 9: r = core + 2z; LayerNorm ---------------------------
__global__ void ln_kernel(const float* __restrict__ ln_w,
                          const float* __restrict__ ln_b,
                          float* __restrict__ out) {
    int row = blockIdx.x;
    int d = threadIdx.x;
    float r = g_core[row * D_MODEL + d] + 2.0f * g_z[row * D_MODEL + d];
    float s = r;
    #pragma unroll
    for (int o = 16; o; o >>= 1) s += __shfl_xor_sync(0xffffffffu, s, o);
    __shared__ float a4[4], b4[4];
    if ((d & 31) == 0) a4[d >> 5] = s;
    __syncthreads();
    float mu = (a4[0] + a4[1] + a4[2] + a4[3]) * (1.0f / 128.0f);
    float c = r - mu;
    float q = c * c;
    #pragma unroll
    for (int o = 16; o; o >>= 1) q += __shfl_xor_sync(0xffffffffu, q, o);
    if ((d & 31) == 0) b4[d >> 5] = q;
    __syncthreads();
    float var = (b4[0] + b4[1] + b4[2] + b4[3]) * (1.0f / 128.0f);
    out[row * D_MODEL + d] = c * rsqrtf(var + EPS) * ln_w[d] + ln_b[d];
}

// ---------------- launch --------------------------------------------------------
extern "C" void kernel_launch(void* const* d_in, const int* in_sizes, int n_in,
                              void* d_out, int out_size) {
    const float* z_seq      = (const float*)d_in[0];
    const float* aux_tensor = (const float*)d_in[1];
    const float* aux_W      = (const float*)d_in[2];
    const float* aux_b      = (const float*)d_in[3];
    const float* ln_w       = (const float*)d_in[4];
    const float* ln_b       = (const float*)d_in[5];
    const float* rms_w      = (const float*)d_in[6];
    const float* in_proj_W  = (const float*)d_in[7];
    const float* conv_W     = (const float*)d_in[8];
    const float* conv_b     = (const float*)d_in[9];
    const float* x_proj_W   = (const float*)d_in[10];
    const float* dt_W       = (const float*)d_in[11];
    const float* dt_b       = (const float*)d_in[12];
    const float* A_log      = (const float*)d_in[13];
    const float* D_param    = (const float*)d_in[14];
    const float* out_proj_W = (const float*)d_in[15];
    float* out = (float*)d_out;

    float *p_zn, *p_xz, *p_xs, *p_dbc, *p_yg, *p_core;
    cudaGetSymbolAddress((void**)&p_zn,   g_zn);
    cudaGetSymbolAddress((void**)&p_xz,   g_xz);
    cudaGetSymbolAddress((void**)&p_xs,   g_xs);
    cudaGetSymbolAddress((void**)&p_dbc,  g_dbc);
    cudaGetSymbolAddress((void**)&p_yg,   g_yg);
    cudaGetSymbolAddress((void**)&p_core, g_core);

    // 1. pre: z + rmsnorm
    pre_kernel<<<ROWS, 128>>>(z_seq, aux_tensor, aux_W, aux_b, rms_w);

    // 2. in_proj: xz = zn @ in_proj_W^T   (4096 x 512, K=128)  [tf32 MMA]
    gemm_tf32_nt<<<dim3(512 / BN, ROWS / BM), 256>>>(p_zn, in_proj_W, p_xz,
                                                     ROWS, 2 * ED, D_MODEL);

    // 3. depthwise conv + silu
    conv_kernel<<<(ROWS * ED) / 256, 256>>>(conv_W, conv_b);

    // 4. x_proj: dbc = xs @ x_proj_W^T    (4096 x 136, K=256)  [tf32 MMA]
    gemm_tf32_nt<<<dim3(3, ROWS / BM), 256>>>(p_xs, x_proj_W, p_dbc,
                                              ROWS, 136, ED);

    // 5. delta + dxs (transposed (b,e,t) layout for the scan)
    delta_kernel<<<dim3(T_LEN / 64, B_SZ), 256>>>(dt_W, dt_b);

    // 6. selective scan + fused gate
    scan_kernel<<<dim3(ED / 8, B_SZ), 256>>>(A_log, D_param);

    // 7. out_proj: core = yg @ out_proj_W^T   (4096 x 128, K=256)  [tf32 MMA]
    gemm_tf32_nt<<<dim3(2, ROWS / BM), 256>>>(p_yg, out_proj_W, p_core,
                                              ROWS, D_MODEL, ED);

    // 8. residual (core + 2z) + LayerNorm
    ln_kernel<<<ROWS, 128>>>(ln_w, ln_b, out);
}